// round 3
// baseline (speedup 1.0000x reference)
#include <cuda_runtime.h>
#include <math.h>

// ---------------------------------------------------------------------------
// EvidentialGNN3D: 3 rounds of edge message passing + graph readout.
//   geo = [len, sum|c_f|, c_f.c_t, c_f.ev]   (round-invariant)
//   msg = tanh([state[f], geo] @ W_msg + b_msg)
//   state' = state + segment_sum(msg, to)
// Restructured:
//   h[f]  = state[f] @ W_msg[0:10] + b_msg + sum|c_f| * W_msg[11]   (per node)
//   msg_j = tanh(h[f][j] + len*W[10][j] + dot1*W[12][j] + dot2*W[13][j])
// State rows padded to 12 floats for aligned red.global.add.v4/v2.f32.
// ---------------------------------------------------------------------------

#define NMAX 200064
#define GMAX 2048
#define SDP  12    // padded state dim (10 used)

// Static scratch (allocation-free rule): ~32 MB total.
__device__ float4 g_state[2][NMAX * 3];   // ping-pong state, (N,12) as float4[3]
__device__ float4 g_h[NMAX * 3];          // per-node message bias h, (N,12)
__device__ float4 g_pc[NMAX];             // (x, y, z, sum|c|)
__device__ float4 g_gs[GMAX * 3];         // per-graph state accumulator (G,12)

__device__ __forceinline__ float tanh_fast(float x) {
    // tanh(x) = 1 - 2/(e^{2x}+1); __expf/__fdividef saturate correctly at +-inf.
    float e = __expf(2.0f * x);
    return 1.0f - __fdividef(2.0f, e + 1.0f);
}

__device__ __forceinline__ void red_add4(float* p, float a, float b, float c, float d) {
    unsigned long long gp = __cvta_generic_to_global((void*)p);
    asm volatile("red.global.add.v4.f32 [%0], {%1,%2,%3,%4};"
                 :: "l"(gp), "f"(a), "f"(b), "f"(c), "f"(d) : "memory");
}
__device__ __forceinline__ void red_add2(float* p, float a, float b) {
    unsigned long long gp = __cvta_generic_to_global((void*)p);
    asm volatile("red.global.add.v2.f32 [%0], {%1,%2};"
                 :: "l"(gp), "f"(a), "f"(b) : "memory");
}

// ---- init: padded coords + zero state[0] + zero graph accumulators ----
__global__ void k_init(const float* __restrict__ coords, int N) {
    int n = blockIdx.x * blockDim.x + threadIdx.x;
    float4 z4 = make_float4(0.f, 0.f, 0.f, 0.f);
    if (n < N) {
        float x = coords[3 * n + 0];
        float y = coords[3 * n + 1];
        float z = coords[3 * n + 2];
        g_pc[n] = make_float4(x, y, z, fabsf(x) + fabsf(y) + fabsf(z));
        g_state[0][n * 3 + 0] = z4;
        g_state[0][n * 3 + 1] = z4;
        g_state[0][n * 3 + 2] = z4;
    }
    if (n < GMAX) {
        g_gs[n * 3 + 0] = z4;
        g_gs[n * 3 + 1] = z4;
        g_gs[n * 3 + 2] = z4;
    }
}

// ---- per-node h = state @ Ws + b + sumabs*W11 ; also copy state->next ----
__global__ void k_h(const float* __restrict__ Wm, const float* __restrict__ bm,
                    int N, int cur) {
    int n = blockIdx.x * blockDim.x + threadIdx.x;
    if (n >= N) return;
    const float4* srow = &g_state[cur][n * 3];
    float4 s0 = srow[0], s1 = srow[1], s2 = srow[2];
    float s[10] = { s0.x, s0.y, s0.z, s0.w, s1.x, s1.y, s1.z, s1.w, s2.x, s2.y };
    float sa = g_pc[n].w;
    float h[10];
#pragma unroll
    for (int j = 0; j < 10; j++) {
        float acc = fmaf(sa, __ldg(&Wm[11 * 10 + j]), __ldg(&bm[j]));
#pragma unroll
        for (int i = 0; i < 10; i++)
            acc = fmaf(s[i], __ldg(&Wm[i * 10 + j]), acc);
        h[j] = acc;
    }
    float4* hrow = &g_h[n * 3];
    hrow[0] = make_float4(h[0], h[1], h[2], h[3]);
    hrow[1] = make_float4(h[4], h[5], h[6], h[7]);
    hrow[2] = make_float4(h[8], h[9], 0.f, 0.f);
    float4* drow = &g_state[cur ^ 1][n * 3];
    drow[0] = s0; drow[1] = s1; drow[2] = s2;
}

// ---- per-edge messages + vectorized atomic scatter into state[nxt] ----
__global__ void __launch_bounds__(256)
k_edge(const int* __restrict__ efrom, const int* __restrict__ eto,
       const float* __restrict__ elen, const float* __restrict__ evec,
       const float* __restrict__ Wm, int E, int nxt, int T) {
    int tid = blockIdx.x * blockDim.x + threadIdx.x;
    // Hoisted weight rows (len=10, dot1=12, dot2=13): 30 regs, amortized 4 edges.
    float wl[10], w2[10], w3[10];
#pragma unroll
    for (int j = 0; j < 10; j++) {
        wl[j] = __ldg(&Wm[100 + j]);
        w2[j] = __ldg(&Wm[120 + j]);
        w3[j] = __ldg(&Wm[130 + j]);
    }
    float* stt = (float*)&g_state[nxt][0];
    for (int e = tid; e < E; e += T) {
        int f = efrom[e];
        int t = eto[e];
        float4 cf = g_pc[f];
        float4 ct = g_pc[t];
        float len = elen[e];
        float v0 = evec[3 * e + 0];
        float v1 = evec[3 * e + 1];
        float v2v = evec[3 * e + 2];
        float dot1 = fmaf(cf.x, ct.x, fmaf(cf.y, ct.y, cf.z * ct.z));
        float dot2 = fmaf(cf.x, v0, fmaf(cf.y, v1, cf.z * v2v));
        const float4* hrow = &g_h[f * 3];
        float4 h0 = hrow[0], h1 = hrow[1], h2 = hrow[2];
        float hv[10] = { h0.x, h0.y, h0.z, h0.w, h1.x, h1.y, h1.z, h1.w, h2.x, h2.y };
        float m[10];
#pragma unroll
        for (int j = 0; j < 10; j++) {
            float a = fmaf(len, wl[j], fmaf(dot1, w2[j], fmaf(dot2, w3[j], hv[j])));
            m[j] = tanh_fast(a);
        }
        float* dst = stt + (size_t)t * SDP;
        red_add4(dst,     m[0], m[1], m[2], m[3]);
        red_add4(dst + 4, m[4], m[5], m[6], m[7]);
        red_add2(dst + 8, m[8], m[9]);
    }
}

// ---- graph segment sum (atomic; light contention, tiny table) ----
__global__ void k_graph(const int* __restrict__ gidx, int N, int fin) {
    int n = blockIdx.x * blockDim.x + threadIdx.x;
    if (n >= N) return;
    int g = gidx[n];
    const float4* srow = &g_state[fin][n * 3];
    float4 s0 = srow[0], s1 = srow[1], s2 = srow[2];
    float* dst = (float*)&g_gs[g * 3];
    red_add4(dst,     s0.x, s0.y, s0.z, s0.w);
    red_add4(dst + 4, s1.x, s1.y, s1.z, s1.w);
    red_add2(dst + 8, s2.x, s2.y);
}

__device__ __forceinline__ float softplus_acc(float x) {
    if (x > 20.f) return x;
    return log1pf(expf(x));
}

// ---- readout: (G,10) @ (10,4) + bias, evidential transforms ----
__global__ void k_out(const float* __restrict__ Wo, const float* __restrict__ bo,
                      float* __restrict__ out, int G) {
    int g = blockIdx.x * blockDim.x + threadIdx.x;
    if (g >= G) return;
    const float* gs = (const float*)&g_gs[g * 3];
    float e[4];
#pragma unroll
    for (int j = 0; j < 4; j++) {
        float acc = __ldg(&bo[j]);
#pragma unroll
        for (int i = 0; i < 10; i++)
            acc = fmaf(gs[i], __ldg(&Wo[i * 4 + j]), acc);
        e[j] = acc;
    }
    out[4 * g + 0] = e[0];
    out[4 * g + 1] = softplus_acc(e[1]);
    out[4 * g + 2] = softplus_acc(e[2]) + 1.0f;
    out[4 * g + 3] = softplus_acc(e[3]);
}

extern "C" void kernel_launch(void* const* d_in, const int* in_sizes, int n_in,
                              void* d_out, int out_size) {
    const float* coords = (const float*)d_in[0];
    const float* elen   = (const float*)d_in[1];
    const float* evec   = (const float*)d_in[2];
    const float* Wm     = (const float*)d_in[3];
    const float* bm     = (const float*)d_in[4];
    const float* Wo     = (const float*)d_in[5];
    const float* bo     = (const float*)d_in[6];
    const int*   efrom  = (const int*)d_in[7];
    const int*   eto    = (const int*)d_in[8];
    const int*   gidx   = (const int*)d_in[9];
    float* out = (float*)d_out;

    int E = in_sizes[7];
    int N = in_sizes[9];
    int G = out_size / 4;

    const int TB = 256;
    int init_count = (N > GMAX) ? N : GMAX;
    int init_blocks = (init_count + TB - 1) / TB;
    int node_blocks = (N + TB - 1) / TB;
    // 4 edges per thread
    long ethreads = ((long)E + 3) / 4;
    int eblocks = (int)((ethreads + TB - 1) / TB);
    int T = eblocks * TB;
    int gblocks = (G + TB - 1) / TB;

    k_init<<<init_blocks, TB>>>(coords, N);
    int cur = 0;
    for (int r = 0; r < 3; r++) {
        k_h<<<node_blocks, TB>>>(Wm, bm, N, cur);
        k_edge<<<eblocks, TB>>>(efrom, eto, elen, evec, Wm, E, cur ^ 1, T);
        cur ^= 1;
    }
    k_graph<<<node_blocks, TB>>>(gidx, N, cur);
    k_out<<<gblocks, TB>>>(Wo, bo, out, G);
}